// round 14
// baseline (speedup 1.0000x reference)
#include <cuda_runtime.h>

#define HH 224
#define WW 224
#define CH 32
#define TM 4
#define NB 8
#define PITCH 65          // odd -> conflict-free x-contiguous LDS
#define PMAXH 64
#define PMAXW 64

// Block (32,16)=512 threads, one 32x32 output tile per (t,c).
// Fast path: per plane, stage the source patch (bbox of the projective quad,
// <=64x64) into smem with ~22 coalesced float4 LDGs, then 4-corner gather via
// LDS. Cuts the LDG instruction count ~5.8x (kernel is LSU-dispatch bound).
// Store path unchanged: smem transpose tile + STG.128.
// Fallback (rare; big/degenerate quads): proven direct-LDG path.
__global__ __launch_bounds__(512)
void persp_kernel(const float* __restrict__ in,
                  const float* __restrict__ wt,
                  float* __restrict__ out)
{
    __shared__ float patch[2][PMAXH * PITCH];   // 33.3 KB
    __shared__ float tile[2][32][33];           // 8.4 KB

    const int tx  = threadIdx.x;        // i_local (gather-contiguous axis)
    const int ty  = threadIdx.y;        // j_local base (handles ty, ty+16)
    const int tid = ty * 32 + tx;
    const int j0 = blockIdx.x * 32;
    const int i0 = blockIdx.y * 32;
    const int oc = blockIdx.z;          // oc = c*TM + t
    const int c  = oc >> 2;
    const int t  = oc & 3;

    const float* m = wt + ((t * CH) + c) * 8;
    const float m0 = m[0], m1 = m[1], m2 = m[2];
    const float m3 = m[3], m4 = m[4], m5 = m[5];
    const float m6 = m[6], m7 = m[7];

    const float step = 2.0f / 223.0f;
    const int i = i0 + tx;
    const float xl = fmaf((float)i, step, -1.0f);   // linspace along H (i)

    // ---- Per-pixel coords/weights (2 j-halves), EXACT reference math ----
    int   x0h[2], x1h[2], y0h[2], y1h[2];
    float wa[2], wb[2], wc[2], wd[2];

    #pragma unroll
    for (int h = 0; h < 2; h++) {
        const int j = j0 + ty + 16 * h;
        const float yl = fmaf((float)j, step, -1.0f);

        const float X = fmaf(m0, xl, fmaf(m1, yl, m2));
        const float Y = fmaf(m3, xl, fmaf(m4, yl, m5));
        const float O = fmaf(m6, xl, fmaf(m7, yl, 1.0f));
        const float r = 1.0f / O;                   // accurate recip
        const float xs = X * r;
        const float ys = Y * r;

        const float x = 0.5f * ((xs + 1.0f) * 222.0f);
        const float y = 0.5f * ((ys + 1.0f) * 222.0f);

        int x0 = (int)floorf(x), x1 = x0 + 1;
        int y0 = (int)floorf(y), y1 = y0 + 1;
        x0 = min(max(x0, 0), WW - 1);
        x1 = min(max(x1, 0), WW - 1);
        y0 = min(max(y0, 0), HH - 1);
        y1 = min(max(y1, 0), HH - 1);
        const float x0f = (float)x0, x1f = (float)x1;
        const float y0f = (float)y0, y1f = (float)y1;

        // Reference's exact (quirky) weights: wb uses (y1f - y0f).
        wa[h] = (x1f - x) * (y1f - y);
        wb[h] = (x1f - x) * (y1f - y0f);
        wc[h] = (x - x0f) * (y1f - y);
        wd[h] = (x - x0f) * (y - y0f);

        x0h[h] = x0; x1h[h] = x1; y0h[h] = y0; y1h[h] = y1;
    }

    // ---- Source bbox from the 4 tile corners (projective => extremes at
    //      corners while O is sign-constant; O affine => check corners) ----
    float xmn =  1e30f, xmx = -1e30f, ymn =  1e30f, ymx = -1e30f;
    float omn =  1e30f, omx = -1e30f;
    #pragma unroll
    for (int cc = 0; cc < 4; cc++) {
        const int ci = i0 + (cc & 1) * 31;
        const int cj = j0 + (cc >> 1) * 31;
        const float cxl = fmaf((float)ci, step, -1.0f);
        const float cyl = fmaf((float)cj, step, -1.0f);
        const float X = fmaf(m0, cxl, fmaf(m1, cyl, m2));
        const float Y = fmaf(m3, cxl, fmaf(m4, cyl, m5));
        const float O = fmaf(m6, cxl, fmaf(m7, cyl, 1.0f));
        omn = fminf(omn, O); omx = fmaxf(omx, O);
        const float r = 1.0f / O;
        const float x = 0.5f * ((X * r + 1.0f) * 222.0f);
        const float y = 0.5f * ((Y * r + 1.0f) * 222.0f);
        xmn = fminf(xmn, x); xmx = fmaxf(xmx, x);
        ymn = fminf(ymn, y); ymx = fmaxf(ymx, y);
    }
    bool use_patch = (omn > 0.0f) || (omx < 0.0f);  // O nonzero on whole tile

    // +/-1 px FP-safety margin; clamp mirrors the per-pixel clamp.
    const int xa_i = min(max((int)floorf(xmn) - 1, 0), WW - 1);
    const int xb_i = min(max((int)floorf(xmx) + 2, 0), WW - 1);
    const int ya   = min(max((int)floorf(ymn) - 1, 0), HH - 1);
    const int yb   = min(max((int)floorf(ymx) + 2, 0), HH - 1);
    const int xa   = xa_i & ~3;                      // float4-align window
    const int Wp   = xb_i - xa + 1;
    const int Hp   = yb - ya + 1;
    use_patch = use_patch && (Wp <= PMAXW) && (Hp <= PMAXH);

    const int plane = HH * WW;
    const size_t nstride = (size_t)CH * plane;
    const float* inp = in + (size_t)c * plane;
    float* const obase = out + (size_t)oc * plane;

    // Store-phase mapping (tid < 256): one STG.128 quad per plane.
    const int i_loc = (tid & 255) >> 3;
    const int jc    = tid & 7;

    if (use_patch) {
        const int f4w = (Wp + 3) >> 2;              // float4 chunks per row

        // Local (patch) gather offsets.
        int lo[2], ldx[2], ldy[2];
        #pragma unroll
        for (int h = 0; h < 2; h++) {
            lo[h]  = (y0h[h] - ya) * PITCH + (x0h[h] - xa);
            ldx[h] = x1h[h] - x0h[h];
            ldy[h] = (y1h[h] - y0h[h]) * PITCH;
        }

        // Staging map: chunk k covers row r=s>>4, col4=s&15 (s=tid+512k).
        int   rr[2], cc4[2];
        bool  act[2];
        #pragma unroll
        for (int k = 0; k < 2; k++) {
            const int s = tid + 512 * k;
            rr[k]  = s >> 4;
            cc4[k] = s & 15;
            act[k] = (rr[k] < Hp) && (cc4[k] < f4w);
        }

        // Prologue: plane 0 -> patch[0]; prefetch plane 1 into regs.
        float4 pre[2];
        #pragma unroll
        for (int k = 0; k < 2; k++)
            if (act[k])
                pre[k] = *(const float4*)(inp + (size_t)(ya + rr[k]) * WW + xa + 4 * cc4[k]);
        #pragma unroll
        for (int k = 0; k < 2; k++)
            if (act[k]) {
                float* d = &patch[0][rr[k] * PITCH + 4 * cc4[k]];
                d[0] = pre[k].x; d[1] = pre[k].y; d[2] = pre[k].z; d[3] = pre[k].w;
            }
        #pragma unroll
        for (int k = 0; k < 2; k++)
            if (act[k])
                pre[k] = *(const float4*)(inp + nstride + (size_t)(ya + rr[k]) * WW + xa + 4 * cc4[k]);
        __syncthreads();                            // publish patch[0]

        #pragma unroll
        for (int n = 0; n < NB; n++) {
            const int b = n & 1;

            // Gather from smem patch (conflict-free: x contiguous, pitch odd).
            const float* P = patch[b];
            #pragma unroll
            for (int h = 0; h < 2; h++) {
                const float Ia = P[lo[h]];
                const float Ic = P[lo[h] + ldx[h]];
                const float Ib = P[lo[h] + ldy[h]];
                const float Id = P[lo[h] + ldy[h] + ldx[h]];
                tile[b][ty + 16 * h][tx] =
                    wa[h] * Ia + wb[h] * Ib + wc[h] * Ic + wd[h] * Id;
            }

            // Stage plane n+1 (in regs) into the other patch buffer.
            if (n < NB - 1) {
                #pragma unroll
                for (int k = 0; k < 2; k++)
                    if (act[k]) {
                        float* d = &patch[b ^ 1][rr[k] * PITCH + 4 * cc4[k]];
                        d[0] = pre[k].x; d[1] = pre[k].y; d[2] = pre[k].z; d[3] = pre[k].w;
                    }
            }
            // Prefetch plane n+2 into regs (consumed after next barrier).
            if (n < NB - 2) {
                #pragma unroll
                for (int k = 0; k < 2; k++)
                    if (act[k])
                        pre[k] = *(const float4*)(inp + (size_t)(n + 2) * nstride
                                                  + (size_t)(ya + rr[k]) * WW + xa + 4 * cc4[k]);
            }

            // One barrier: publishes tile[b] + patch[b^1]; WAR-safe by the
            // previous barrier (readers of both finished before it).
            __syncthreads();

            // Store plane n: transposed LDS (pad-33, conflict-free), STG.128.
            if (tid < 256) {
                float4 r4;
                r4.x = tile[b][4 * jc + 0][i_loc];
                r4.y = tile[b][4 * jc + 1][i_loc];
                r4.z = tile[b][4 * jc + 2][i_loc];
                r4.w = tile[b][4 * jc + 3][i_loc];
                *(float4*)(obase + (size_t)n * TM * nstride
                           + (size_t)(i0 + i_loc) * WW + (j0 + 4 * jc)) = r4;
            }
        }
    } else {
        // ---- Fallback: proven direct-LDG path (rare) ----
        int o0[2], o1[2], o2[2], o3[2];
        #pragma unroll
        for (int h = 0; h < 2; h++) {
            o0[h] = y0h[h] * WW + x0h[h];
            o1[h] = y0h[h] * WW + x1h[h];
            o2[h] = y1h[h] * WW + x0h[h];
            o3[h] = y1h[h] * WW + x1h[h];
        }
        #pragma unroll
        for (int n = 0; n < NB; n++) {
            const int b = n & 1;
            const float* p = inp + (size_t)n * nstride;
            #pragma unroll
            for (int h = 0; h < 2; h++) {
                const float Ia = __ldg(p + o0[h]);
                const float Ic = __ldg(p + o1[h]);
                const float Ib = __ldg(p + o2[h]);
                const float Id = __ldg(p + o3[h]);
                tile[b][ty + 16 * h][tx] =
                    wa[h] * Ia + wb[h] * Ib + wc[h] * Ic + wd[h] * Id;
            }
            __syncthreads();
            if (tid < 256) {
                float4 r4;
                r4.x = tile[b][4 * jc + 0][i_loc];
                r4.y = tile[b][4 * jc + 1][i_loc];
                r4.z = tile[b][4 * jc + 2][i_loc];
                r4.w = tile[b][4 * jc + 3][i_loc];
                *(float4*)(obase + (size_t)n * TM * nstride
                           + (size_t)(i0 + i_loc) * WW + (j0 + 4 * jc)) = r4;
            }
            __syncthreads();
        }
    }
}

extern "C" void kernel_launch(void* const* d_in, const int* in_sizes, int n_in,
                              void* d_out, int out_size)
{
    const float* in = (const float*)d_in[0];   // inputs  (8,32,224,224) f32
    const float* wt = (const float*)d_in[1];   // wt_pers (4,32,8)       f32
    float* out = (float*)d_out;                // (8,128,224,224) f32

    dim3 block(32, 16);
    dim3 grid(WW / 32, HH / 32, CH * TM);      // 7 x 7 x 128
    persp_kernel<<<grid, block>>>(in, wt, out);
}

// round 17
// speedup vs baseline: 1.3057x; 1.3057x over previous
#include <cuda_runtime.h>

#define HH 224
#define WW 224
#define CH 32
#define TM 4
#define NB 8

// Block (32,8)=256 threads, one 32x32 output tile per (t,c).
// Each thread: i = i0+tx, j quad = j0+4*ty..+3  -> gather result is a float4.
// All non-gather memory ops vectorized: STS.128 into XOR-swizzled float4 tile,
// LDS.128 out, STG.128 to gmem. Mem-instr per elem*plane: 4 LDG + 0.75 vec
// (was 6.25 scalar-equivalent in the 94.8us kernel).
__global__ __launch_bounds__(256)
void persp_kernel(const float* __restrict__ in,
                  const float* __restrict__ wt,
                  float* __restrict__ out)
{
    __shared__ float4 tile4[2][32][8];   // [buf][i_local][j-quad, XOR-swizzled]

    const int tx  = threadIdx.x;         // i_local
    const int ty  = threadIdx.y;         // j-quad index (0..7)
    const int tid = ty * 32 + tx;
    const int j0 = blockIdx.x * 32;
    const int i0 = blockIdx.y * 32;
    const int oc = blockIdx.z;           // oc = c*TM + t
    const int c  = oc >> 2;
    const int t  = oc & 3;

    const float* m = wt + ((t * CH) + c) * 8;
    const float m0 = m[0], m1 = m[1], m2 = m[2];
    const float m3 = m[3], m4 = m[4], m5 = m[5];
    const float m6 = m[6], m7 = m[7];

    const float step = 2.0f / 223.0f;
    const int i = i0 + tx;
    const float xl = fmaf((float)i, step, -1.0f);   // linspace along H (i)

    // ---- Per-pixel coords/weights for the 4 j's of this thread ----
    int   o0[4], o1[4], o2[4], o3[4];
    float wa[4], wb[4], wc[4], wd[4];

    #pragma unroll
    for (int k = 0; k < 4; k++) {
        const int j = j0 + 4 * ty + k;
        const float yl = fmaf((float)j, step, -1.0f);

        const float X = fmaf(m0, xl, fmaf(m1, yl, m2));
        const float Y = fmaf(m3, xl, fmaf(m4, yl, m5));
        const float O = fmaf(m6, xl, fmaf(m7, yl, 1.0f));
        const float r = 1.0f / O;                   // accurate recip
        const float xs = X * r;
        const float ys = Y * r;

        const float x = 0.5f * ((xs + 1.0f) * 222.0f);
        const float y = 0.5f * ((ys + 1.0f) * 222.0f);

        int x0 = (int)floorf(x), x1 = x0 + 1;
        int y0 = (int)floorf(y), y1 = y0 + 1;
        x0 = min(max(x0, 0), WW - 1);
        x1 = min(max(x1, 0), WW - 1);
        y0 = min(max(y0, 0), HH - 1);
        y1 = min(max(y1, 0), HH - 1);
        const float x0f = (float)x0, x1f = (float)x1;
        const float y0f = (float)y0, y1f = (float)y1;

        // Reference's exact (quirky) weights: wb uses (y1f - y0f).
        wa[k] = (x1f - x) * (y1f - y);
        wb[k] = (x1f - x) * (y1f - y0f);
        wc[k] = (x - x0f) * (y1f - y);
        wd[k] = (x - x0f) * (y - y0f);

        const int ba  = y0 * WW + x0;
        const int dx  = x1 - x0;
        const int dyW = (y1 - y0) * WW;
        o0[k] = ba;
        o1[k] = ba + dx;
        o2[k] = ba + dyW;
        o3[k] = ba + dyW + dx;
    }

    const int plane = HH * WW;
    const size_t nstride = (size_t)CH * plane;      // elements per batch image
    const float* inp = in + (size_t)c * plane;
    float* const obase = out + (size_t)oc * plane;

    // Store-phase mapping: 256 threads -> 256 quads (full 32x32 plane tile).
    const int i_loc = tid >> 3;          // 0..31
    const int jc    = tid & 7;           // float4 chunk along j
    float* const oq = obase + (size_t)(i0 + i_loc) * WW + (j0 + 4 * jc);
    const int jswz = jc ^ (i_loc & 7);   // read-side XOR swizzle

    #pragma unroll
    for (int n = 0; n < NB; n++) {
        const int b = n & 1;
        const float* p = inp + (size_t)n * nstride;

        // ---- Gather: 16 independent LDGs in flight ----
        float va[4], vb[4], vc[4], vd[4];
        #pragma unroll
        for (int k = 0; k < 4; k++) {
            va[k] = __ldg(p + o0[k]);
            vc[k] = __ldg(p + o1[k]);
            vb[k] = __ldg(p + o2[k]);
            vd[k] = __ldg(p + o3[k]);
        }

        float4 r4;
        r4.x = wa[0] * va[0] + wb[0] * vb[0] + wc[0] * vc[0] + wd[0] * vd[0];
        r4.y = wa[1] * va[1] + wb[1] * vb[1] + wc[1] * vc[1] + wd[1] * vd[1];
        r4.z = wa[2] * va[2] + wb[2] * vb[2] + wc[2] * vc[2] + wd[2] * vd[2];
        r4.w = wa[3] * va[3] + wb[3] * vb[3] + wc[3] * vc[3] + wd[3] * vd[3];

        // STS.128, XOR-swizzled: lanes (tx) hit disjoint 16B ranges per phase.
        tile4[b][tx][ty ^ (tx & 7)] = r4;

        // One barrier per plane: publishes tile4[b]; WAR on buffer b is
        // guaranteed by the previous plane's barrier (readers done before it).
        __syncthreads();

        // ---- Store: LDS.128 (contiguous 512B per warp) + STG.128 ----
        const float4 q4 = tile4[b][i_loc][jswz];
        *(float4*)(oq + (size_t)n * TM * nstride) = q4;
    }
}

extern "C" void kernel_launch(void* const* d_in, const int* in_sizes, int n_in,
                              void* d_out, int out_size)
{
    const float* in = (const float*)d_in[0];   // inputs  (8,32,224,224) f32
    const float* wt = (const float*)d_in[1];   // wt_pers (4,32,8)       f32
    float* out = (float*)d_out;                // (8,128,224,224) f32

    dim3 block(32, 8);
    dim3 grid(WW / 32, HH / 32, CH * TM);      // 7 x 7 x 128
    persp_kernel<<<grid, block>>>(in, wt, out);
}